// round 1
// baseline (speedup 1.0000x reference)
#include <cuda_runtime.h>
#include <cuda_bf16.h>
#include <cstdint>

#define B_SZ 2
#define SEQ 2048
#define ROWS (B_SZ * SEQ)          // 4096
#define D_MODEL 128
#define D_INNER 1024
#define NHEADS 8
#define HEADDIM 128
#define D_STATE 128
#define D_CONV 4
#define CONV_DIM (D_INNER + 2 * D_STATE)   // 1280
#define D_IN_PROJ (2 * D_INNER + 2 * D_STATE + NHEADS)  // 2312
#define EPS 1e-5f

// ---------------- scratch (no allocations allowed) ----------------
__device__ float g_h1[ROWS * D_MODEL];            // ln1 output
__device__ float g_zx[ROWS * D_IN_PROJ];          // in_proj output (z | xBC | dt_raw)
__device__ float g_xbc[ROWS * CONV_DIM];          // conv+silu output
__device__ float g_dt[ROWS * NHEADS];
__device__ float g_dA[ROWS * NHEADS];
__device__ float g_y[ROWS * D_INNER];             // scan output (+ D skip)
__device__ float g_g[ROWS * D_INNER];             // gated + rmsnormed
__device__ float g_res2[ROWS * D_MODEL];          // mixer out + residual
__device__ float g_h2[ROWS * D_MODEL];            // ln2 output

// ---------------- helpers ----------------
__device__ __forceinline__ float siluf(float v) {
    return v / (1.0f + expf(-v));
}

// ---------------- LayerNorm: one block (128 thr) per row ----------------
__global__ __launch_bounds__(128) void ln_kernel(
    const float* __restrict__ x, const float* __restrict__ w,
    const float* __restrict__ b, float* __restrict__ out)
{
    int row = blockIdx.x;
    int tid = threadIdx.x;
    __shared__ float sm[4];
    float v = x[(size_t)row * D_MODEL + tid];

    float s = v;
    #pragma unroll
    for (int o = 16; o; o >>= 1) s += __shfl_xor_sync(0xffffffffu, s, o);
    if ((tid & 31) == 0) sm[tid >> 5] = s;
    __syncthreads();
    float mean = (sm[0] + sm[1] + sm[2] + sm[3]) * (1.0f / 128.0f);
    __syncthreads();

    float d = v - mean;
    float q = d * d;
    #pragma unroll
    for (int o = 16; o; o >>= 1) q += __shfl_xor_sync(0xffffffffu, q, o);
    if ((tid & 31) == 0) sm[tid >> 5] = q;
    __syncthreads();
    float var = (sm[0] + sm[1] + sm[2] + sm[3]) * (1.0f / 128.0f);

    out[(size_t)row * D_MODEL + tid] = d * rsqrtf(var + EPS) * w[tid] + b[tid];
}

// ---------------- Generic TN GEMM: C[M,N] = A[M,K] @ W[N,K]^T ----------------
// BM=BN=64, BK=32, 256 threads, 4x4 register tile. M must be multiple of 64.
template<bool RESID, bool BIAS>
__global__ __launch_bounds__(256) void gemm_tn(
    const float* __restrict__ A, int lda,
    const float* __restrict__ W, int ldw,
    float* __restrict__ C, int ldc,
    int N, int K,
    const float* __restrict__ resid,
    const float* __restrict__ bias)
{
    __shared__ float As[32][68];
    __shared__ float Ws[32][68];

    int tid = threadIdx.x;
    int tx = tid & 15;          // n-tile coord
    int ty = tid >> 4;          // m-tile coord
    int m0 = blockIdx.y * 64;
    int n0 = blockIdx.x * 64;

    int arow = tid >> 3;        // 0..31
    int kv = (tid & 7) * 4;     // k-offset within chunk

    float acc[4][4];
    #pragma unroll
    for (int i = 0; i < 4; i++)
        #pragma unroll
        for (int j = 0; j < 4; j++) acc[i][j] = 0.0f;

    for (int k0 = 0; k0 < K; k0 += 32) {
        #pragma unroll
        for (int rr = 0; rr < 2; rr++) {
            int row = arow + rr * 32;
            float4 av = *(const float4*)(A + (size_t)(m0 + row) * lda + k0 + kv);
            As[kv + 0][row] = av.x;
            As[kv + 1][row] = av.y;
            As[kv + 2][row] = av.z;
            As[kv + 3][row] = av.w;
            int wr = n0 + row;
            float4 wv = make_float4(0.f, 0.f, 0.f, 0.f);
            if (wr < N) wv = *(const float4*)(W + (size_t)wr * ldw + k0 + kv);
            Ws[kv + 0][row] = wv.x;
            Ws[kv + 1][row] = wv.y;
            Ws[kv + 2][row] = wv.z;
            Ws[kv + 3][row] = wv.w;
        }
        __syncthreads();

        #pragma unroll
        for (int kk = 0; kk < 32; kk++) {
            float4 a = *(const float4*)&As[kk][ty * 4];
            float4 w = *(const float4*)&Ws[kk][tx * 4];
            float af[4] = {a.x, a.y, a.z, a.w};
            float wf[4] = {w.x, w.y, w.z, w.w};
            #pragma unroll
            for (int i = 0; i < 4; i++)
                #pragma unroll
                for (int j = 0; j < 4; j++)
                    acc[i][j] = fmaf(af[i], wf[j], acc[i][j]);
        }
        __syncthreads();
    }

    #pragma unroll
    for (int i = 0; i < 4; i++) {
        int m = m0 + ty * 4 + i;
        #pragma unroll
        for (int j = 0; j < 4; j++) {
            int n = n0 + tx * 4 + j;
            if (n < N) {
                float o = acc[i][j];
                if (RESID) o += resid[(size_t)m * ldc + n];
                if (BIAS)  o += bias[n];
                C[(size_t)m * ldc + n] = o;
            }
        }
    }
}

// ---------------- depthwise causal conv (k=4) + bias + silu ----------------
__global__ __launch_bounds__(256) void conv_kernel(
    const float* __restrict__ zx, const float* __restrict__ cw,
    const float* __restrict__ cb, float* __restrict__ out)
{
    int idx = blockIdx.x * 256 + threadIdx.x;
    if (idx >= B_SZ * SEQ * CONV_DIM) return;
    int c = idx % CONV_DIM;
    int t = (idx / CONV_DIM) & (SEQ - 1);
    int b = idx / (CONV_DIM * SEQ);

    const float* col = zx + (size_t)b * SEQ * D_IN_PROJ + D_INNER + c;
    float4 w = *(const float4*)(cw + c * 4);
    float acc = cb[c];
    if (t >= 3) acc = fmaf(w.x, col[(size_t)(t - 3) * D_IN_PROJ], acc);
    if (t >= 2) acc = fmaf(w.y, col[(size_t)(t - 2) * D_IN_PROJ], acc);
    if (t >= 1) acc = fmaf(w.z, col[(size_t)(t - 1) * D_IN_PROJ], acc);
    acc = fmaf(w.w, col[(size_t)t * D_IN_PROJ], acc);
    out[idx] = siluf(acc);
}

// ---------------- dt = softplus(raw + bias), dA = exp(dt * -exp(A_log)) ----------------
__global__ __launch_bounds__(256) void dt_kernel(
    const float* __restrict__ zx, const float* __restrict__ dt_bias,
    const float* __restrict__ A_log, float* __restrict__ dt_out,
    float* __restrict__ dA_out)
{
    int idx = blockIdx.x * 256 + threadIdx.x;
    if (idx >= ROWS * NHEADS) return;
    int h = idx & (NHEADS - 1);
    int row = idx >> 3;
    float raw = zx[(size_t)row * D_IN_PROJ + (D_IN_PROJ - NHEADS) + h] + dt_bias[h];
    float dt = (raw > 20.0f) ? raw : log1pf(expf(raw));
    float A = -expf(A_log[h]);
    dt_out[idx] = dt;
    dA_out[idx] = expf(dt * A);
}

// ---------------- recurrent selective scan ----------------
// grid: (32 p-blocks, 8 heads, 2 batches); block: 128 threads
// warp w owns p-row (pb*4 + w); lane g owns state columns [4g, 4g+4)
__global__ __launch_bounds__(128) void scan_kernel(
    const float* __restrict__ xbc, const float* __restrict__ dt_g,
    const float* __restrict__ dA_g, const float* __restrict__ D_skip,
    float* __restrict__ y_out)
{
    int b = blockIdx.z, h = blockIdx.y, pb = blockIdx.x;
    int tid = threadIdx.x;
    int pl = tid >> 5;
    int g = tid & 31;
    int p = pb * 4 + pl;
    float Dsk = D_skip[h];

    const float* xb = xbc + (size_t)b * SEQ * CONV_DIM;
    const float* dtp = dt_g + (size_t)b * SEQ * NHEADS + h;
    const float* dAp = dA_g + (size_t)b * SEQ * NHEADS + h;

    float S0 = 0.f, S1 = 0.f, S2 = 0.f, S3 = 0.f;

    // prefetch t = 0
    float  nx = xb[h * HEADDIM + p];
    float4 nB = *(const float4*)(xb + D_INNER + g * 4);
    float4 nC = *(const float4*)(xb + D_INNER + D_STATE + g * 4);
    float ndt = dtp[0];
    float ndA = dAp[0];

    for (int t = 0; t < SEQ; t++) {
        float  cx = nx;  float4 cB = nB, cC = nC;
        float cdt = ndt; float cdA = ndA;
        if (t + 1 < SEQ) {
            const float* r = xb + (size_t)(t + 1) * CONV_DIM;
            nx  = r[h * HEADDIM + p];
            nB  = *(const float4*)(r + D_INNER + g * 4);
            nC  = *(const float4*)(r + D_INNER + D_STATE + g * 4);
            ndt = dtp[(size_t)(t + 1) * NHEADS];
            ndA = dAp[(size_t)(t + 1) * NHEADS];
        }
        float c0 = cdt * cx;
        S0 = fmaf(S0, cdA, c0 * cB.x);
        S1 = fmaf(S1, cdA, c0 * cB.y);
        S2 = fmaf(S2, cdA, c0 * cB.z);
        S3 = fmaf(S3, cdA, c0 * cB.w);
        float y = S0 * cC.x;
        y = fmaf(S1, cC.y, y);
        y = fmaf(S2, cC.z, y);
        y = fmaf(S3, cC.w, y);
        #pragma unroll
        for (int o = 16; o; o >>= 1) y += __shfl_xor_sync(0xffffffffu, y, o);
        if (g == 0)
            y_out[((size_t)(b * SEQ + t)) * D_INNER + h * HEADDIM + p] = fmaf(Dsk, cx, y);
    }
}

// ---------------- gate with silu(z), then RMSNorm * gnorm_w ----------------
__global__ __launch_bounds__(256) void gate_kernel(
    const float* __restrict__ y, const float* __restrict__ zx,
    const float* __restrict__ gw, float* __restrict__ out)
{
    int row = blockIdx.x;
    int tid = threadIdx.x;
    int d = tid * 4;
    __shared__ float sm[8];

    float4 y4 = *(const float4*)(y + (size_t)row * D_INNER + d);
    float4 z4 = *(const float4*)(zx + (size_t)row * D_IN_PROJ + d);
    float g0 = y4.x * siluf(z4.x);
    float g1 = y4.y * siluf(z4.y);
    float g2 = y4.z * siluf(z4.z);
    float g3 = y4.w * siluf(z4.w);

    float ss = g0 * g0 + g1 * g1 + g2 * g2 + g3 * g3;
    #pragma unroll
    for (int o = 16; o; o >>= 1) ss += __shfl_xor_sync(0xffffffffu, ss, o);
    if ((tid & 31) == 0) sm[tid >> 5] = ss;
    __syncthreads();
    float tot = 0.f;
    #pragma unroll
    for (int i = 0; i < 8; i++) tot += sm[i];
    float scale = rsqrtf(tot * (1.0f / (float)D_INNER) + EPS);

    float4 w4 = *(const float4*)(gw + d);
    float4 o4 = make_float4(g0 * scale * w4.x, g1 * scale * w4.y,
                            g2 * scale * w4.z, g3 * scale * w4.w);
    *(float4*)(out + (size_t)row * D_INNER + d) = o4;
}

// ---------------- launch ----------------
extern "C" void kernel_launch(void* const* d_in, const int* in_sizes, int n_in,
                              void* d_out, int out_size)
{
    const float* hidden  = (const float*)d_in[0];
    const float* w_in    = (const float*)d_in[1];
    const float* conv_w  = (const float*)d_in[2];
    const float* conv_b  = (const float*)d_in[3];
    const float* dt_bias = (const float*)d_in[4];
    const float* A_log   = (const float*)d_in[5];
    const float* D_skip  = (const float*)d_in[6];
    const float* gnorm_w = (const float*)d_in[7];
    const float* w_out   = (const float*)d_in[8];
    const float* ln1_w   = (const float*)d_in[9];
    const float* ln1_b   = (const float*)d_in[10];
    const float* ln2_w   = (const float*)d_in[11];
    const float* ln2_b   = (const float*)d_in[12];
    const float* mlp_w   = (const float*)d_in[13];
    const float* mlp_b   = (const float*)d_in[14];
    float* outp = (float*)d_out;

    float *h1, *zx, *xbc, *dt, *dA, *y, *gg, *res2, *h2;
    cudaGetSymbolAddress((void**)&h1,   g_h1);
    cudaGetSymbolAddress((void**)&zx,   g_zx);
    cudaGetSymbolAddress((void**)&xbc,  g_xbc);
    cudaGetSymbolAddress((void**)&dt,   g_dt);
    cudaGetSymbolAddress((void**)&dA,   g_dA);
    cudaGetSymbolAddress((void**)&y,    g_y);
    cudaGetSymbolAddress((void**)&gg,   g_g);
    cudaGetSymbolAddress((void**)&res2, g_res2);
    cudaGetSymbolAddress((void**)&h2,   g_h2);

    // 1) ln1
    ln_kernel<<<ROWS, 128>>>(hidden, ln1_w, ln1_b, h1);

    // 2) in_proj: [4096,2312] = h1[4096,128] @ w_in[2312,128]^T
    {
        dim3 grid((D_IN_PROJ + 63) / 64, ROWS / 64);
        gemm_tn<false, false><<<grid, 256>>>(h1, D_MODEL, w_in, D_MODEL,
                                             zx, D_IN_PROJ, D_IN_PROJ, D_MODEL,
                                             nullptr, nullptr);
    }

    // 3) conv + silu
    {
        int total = B_SZ * SEQ * CONV_DIM;
        conv_kernel<<<(total + 255) / 256, 256>>>(zx, conv_w, conv_b, xbc);
    }

    // 4) dt / dA
    dt_kernel<<<(ROWS * NHEADS + 255) / 256, 256>>>(zx, dt_bias, A_log, dt, dA);

    // 5) scan
    {
        dim3 grid(HEADDIM / 4, NHEADS, B_SZ);
        scan_kernel<<<grid, 128>>>(xbc, dt, dA, D_skip, y);
    }

    // 6) gate + rmsnorm
    gate_kernel<<<ROWS, 256>>>(y, zx, gnorm_w, gg);

    // 7) out_proj + residual: res2 = gg @ w_out^T + hidden
    {
        dim3 grid((D_MODEL + 63) / 64, ROWS / 64);
        gemm_tn<true, false><<<grid, 256>>>(gg, D_INNER, w_out, D_INNER,
                                            res2, D_MODEL, D_MODEL, D_INNER,
                                            hidden, nullptr);
    }

    // 8) ln2
    ln_kernel<<<ROWS, 128>>>(res2, ln2_w, ln2_b, h2);

    // 9) mlp: out = h2 @ mlp_w^T + mlp_b
    {
        dim3 grid((D_MODEL + 63) / 64, ROWS / 64);
        gemm_tn<false, true><<<grid, 256>>>(h2, D_MODEL, mlp_w, D_MODEL,
                                            outp, D_MODEL, D_MODEL, D_MODEL,
                                            nullptr, mlp_b);
    }
    (void)in_sizes; (void)n_in; (void)out_size;
}

// round 2
// speedup vs baseline: 1.4810x; 1.4810x over previous
#include <cuda_runtime.h>
#include <cuda_bf16.h>
#include <cstdint>

#define B_SZ 2
#define SEQ 2048
#define ROWS (B_SZ * SEQ)          // 4096
#define D_MODEL 128
#define D_INNER 1024
#define NHEADS 8
#define HEADDIM 128
#define D_STATE 128
#define D_CONV 4
#define CONV_DIM (D_INNER + 2 * D_STATE)   // 1280
#define D_IN_PROJ (2 * D_INNER + 2 * D_STATE + NHEADS)  // 2312
#define EPS 1e-5f

#define T_CHUNK 16
#define N_CHUNKS (SEQ / T_CHUNK)   // 128
#define P_BLK 16

// ---------------- scratch (no allocations allowed) ----------------
__device__ float g_h1[ROWS * D_MODEL];
__device__ float g_zx[ROWS * D_IN_PROJ];
__device__ float g_xbc[ROWS * CONV_DIM];
__device__ float g_dt[ROWS * NHEADS];
__device__ float g_dA[ROWS * NHEADS];
__device__ float g_y[ROWS * D_INNER];
__device__ float g_g[ROWS * D_INNER];
__device__ float g_res2[ROWS * D_MODEL];
__device__ float g_h2[ROWS * D_MODEL];

__device__ __forceinline__ float siluf(float v) {
    return v / (1.0f + expf(-v));
}

__device__ __forceinline__ void cp_async16(void* smem_dst, const void* gsrc) {
    unsigned saddr = (unsigned)__cvta_generic_to_shared(smem_dst);
    asm volatile("cp.async.cg.shared.global [%0], [%1], 16;" :: "r"(saddr), "l"(gsrc));
}
__device__ __forceinline__ void cp_async4(void* smem_dst, const void* gsrc) {
    unsigned saddr = (unsigned)__cvta_generic_to_shared(smem_dst);
    asm volatile("cp.async.ca.shared.global [%0], [%1], 4;" :: "r"(saddr), "l"(gsrc));
}
__device__ __forceinline__ void cp_commit() {
    asm volatile("cp.async.commit_group;");
}
template<int N>
__device__ __forceinline__ void cp_wait() {
    asm volatile("cp.async.wait_group %0;" :: "n"(N));
}

// ---------------- LayerNorm: one block (128 thr) per row ----------------
__global__ __launch_bounds__(128) void ln_kernel(
    const float* __restrict__ x, const float* __restrict__ w,
    const float* __restrict__ b, float* __restrict__ out)
{
    int row = blockIdx.x;
    int tid = threadIdx.x;
    __shared__ float sm[4];
    float v = x[(size_t)row * D_MODEL + tid];

    float s = v;
    #pragma unroll
    for (int o = 16; o; o >>= 1) s += __shfl_xor_sync(0xffffffffu, s, o);
    if ((tid & 31) == 0) sm[tid >> 5] = s;
    __syncthreads();
    float mean = (sm[0] + sm[1] + sm[2] + sm[3]) * (1.0f / 128.0f);
    __syncthreads();

    float d = v - mean;
    float q = d * d;
    #pragma unroll
    for (int o = 16; o; o >>= 1) q += __shfl_xor_sync(0xffffffffu, q, o);
    if ((tid & 31) == 0) sm[tid >> 5] = q;
    __syncthreads();
    float var = (sm[0] + sm[1] + sm[2] + sm[3]) * (1.0f / 128.0f);

    out[(size_t)row * D_MODEL + tid] = d * rsqrtf(var + EPS) * w[tid] + b[tid];
}

// ---------------- GEMM 128x64x32, 256 threads, 8x4 regtile ----------------
// C[M,N] = A[M,K] @ W[N,K]^T ; M % 128 == 0
__global__ __launch_bounds__(256) void gemm_tn128(
    const float* __restrict__ A, int lda,
    const float* __restrict__ W, int ldw,
    float* __restrict__ C, int ldc,
    int N, int K)
{
    __shared__ float As[32][132];
    __shared__ float Ws[32][68];

    int tid = threadIdx.x;
    int tx = tid & 15;          // n: 4 each -> 64
    int ty = tid >> 4;          // m: 8 each -> 128
    int m0 = blockIdx.y * 128;
    int n0 = blockIdx.x * 64;

    int arow = tid >> 3;        // 0..31
    int kv = (tid & 7) * 4;

    float acc[8][4];
    #pragma unroll
    for (int i = 0; i < 8; i++)
        #pragma unroll
        for (int j = 0; j < 4; j++) acc[i][j] = 0.0f;

    for (int k0 = 0; k0 < K; k0 += 32) {
        #pragma unroll
        for (int rr = 0; rr < 4; rr++) {
            int row = arow + rr * 32;
            float4 av = *(const float4*)(A + (size_t)(m0 + row) * lda + k0 + kv);
            As[kv + 0][row] = av.x;
            As[kv + 1][row] = av.y;
            As[kv + 2][row] = av.z;
            As[kv + 3][row] = av.w;
        }
        #pragma unroll
        for (int rr = 0; rr < 2; rr++) {
            int row = arow + rr * 32;
            int wr = n0 + row;
            float4 wv = make_float4(0.f, 0.f, 0.f, 0.f);
            if (wr < N) wv = *(const float4*)(W + (size_t)wr * ldw + k0 + kv);
            Ws[kv + 0][row] = wv.x;
            Ws[kv + 1][row] = wv.y;
            Ws[kv + 2][row] = wv.z;
            Ws[kv + 3][row] = wv.w;
        }
        __syncthreads();

        #pragma unroll
        for (int kk = 0; kk < 32; kk++) {
            float4 a0 = *(const float4*)&As[kk][ty * 8];
            float4 a1 = *(const float4*)&As[kk][ty * 8 + 4];
            float4 w  = *(const float4*)&Ws[kk][tx * 4];
            float af[8] = {a0.x, a0.y, a0.z, a0.w, a1.x, a1.y, a1.z, a1.w};
            float wf[4] = {w.x, w.y, w.z, w.w};
            #pragma unroll
            for (int i = 0; i < 8; i++)
                #pragma unroll
                for (int j = 0; j < 4; j++)
                    acc[i][j] = fmaf(af[i], wf[j], acc[i][j]);
        }
        __syncthreads();
    }

    #pragma unroll
    for (int i = 0; i < 8; i++) {
        int m = m0 + ty * 8 + i;
        #pragma unroll
        for (int j = 0; j < 4; j++) {
            int n = n0 + tx * 4 + j;
            if (n < N) C[(size_t)m * ldc + n] = acc[i][j];
        }
    }
}

// ---------------- GEMM 64x64x32 (for small-N gemms) ----------------
template<bool RESID, bool BIAS>
__global__ __launch_bounds__(256) void gemm_tn64(
    const float* __restrict__ A, int lda,
    const float* __restrict__ W, int ldw,
    float* __restrict__ C, int ldc,
    int N, int K,
    const float* __restrict__ resid,
    const float* __restrict__ bias)
{
    __shared__ float As[32][68];
    __shared__ float Ws[32][68];

    int tid = threadIdx.x;
    int tx = tid & 15;
    int ty = tid >> 4;
    int m0 = blockIdx.y * 64;
    int n0 = blockIdx.x * 64;

    int arow = tid >> 3;
    int kv = (tid & 7) * 4;

    float acc[4][4];
    #pragma unroll
    for (int i = 0; i < 4; i++)
        #pragma unroll
        for (int j = 0; j < 4; j++) acc[i][j] = 0.0f;

    for (int k0 = 0; k0 < K; k0 += 32) {
        #pragma unroll
        for (int rr = 0; rr < 2; rr++) {
            int row = arow + rr * 32;
            float4 av = *(const float4*)(A + (size_t)(m0 + row) * lda + k0 + kv);
            As[kv + 0][row] = av.x;
            As[kv + 1][row] = av.y;
            As[kv + 2][row] = av.z;
            As[kv + 3][row] = av.w;
            int wr = n0 + row;
            float4 wv = make_float4(0.f, 0.f, 0.f, 0.f);
            if (wr < N) wv = *(const float4*)(W + (size_t)wr * ldw + k0 + kv);
            Ws[kv + 0][row] = wv.x;
            Ws[kv + 1][row] = wv.y;
            Ws[kv + 2][row] = wv.z;
            Ws[kv + 3][row] = wv.w;
        }
        __syncthreads();

        #pragma unroll
        for (int kk = 0; kk < 32; kk++) {
            float4 a = *(const float4*)&As[kk][ty * 4];
            float4 w = *(const float4*)&Ws[kk][tx * 4];
            float af[4] = {a.x, a.y, a.z, a.w};
            float wf[4] = {w.x, w.y, w.z, w.w};
            #pragma unroll
            for (int i = 0; i < 4; i++)
                #pragma unroll
                for (int j = 0; j < 4; j++)
                    acc[i][j] = fmaf(af[i], wf[j], acc[i][j]);
        }
        __syncthreads();
    }

    #pragma unroll
    for (int i = 0; i < 4; i++) {
        int m = m0 + ty * 4 + i;
        #pragma unroll
        for (int j = 0; j < 4; j++) {
            int n = n0 + tx * 4 + j;
            if (n < N) {
                float o = acc[i][j];
                if (RESID) o += resid[(size_t)m * ldc + n];
                if (BIAS)  o += bias[n];
                C[(size_t)m * ldc + n] = o;
            }
        }
    }
}

// ---------------- depthwise causal conv (k=4) + bias + silu ----------------
__global__ __launch_bounds__(256) void conv_kernel(
    const float* __restrict__ zx, const float* __restrict__ cw,
    const float* __restrict__ cb, float* __restrict__ out)
{
    int idx = blockIdx.x * 256 + threadIdx.x;
    if (idx >= B_SZ * SEQ * CONV_DIM) return;
    int c = idx % CONV_DIM;
    int t = (idx / CONV_DIM) & (SEQ - 1);
    int b = idx / (CONV_DIM * SEQ);

    const float* col = zx + (size_t)b * SEQ * D_IN_PROJ + D_INNER + c;
    float4 w = *(const float4*)(cw + c * 4);
    float acc = cb[c];
    if (t >= 3) acc = fmaf(w.x, col[(size_t)(t - 3) * D_IN_PROJ], acc);
    if (t >= 2) acc = fmaf(w.y, col[(size_t)(t - 2) * D_IN_PROJ], acc);
    if (t >= 1) acc = fmaf(w.z, col[(size_t)(t - 1) * D_IN_PROJ], acc);
    acc = fmaf(w.w, col[(size_t)t * D_IN_PROJ], acc);
    out[idx] = siluf(acc);
}

// ---------------- dt = softplus(raw + bias), dA = exp(dt * -exp(A_log)) ----------------
__global__ __launch_bounds__(256) void dt_kernel(
    const float* __restrict__ zx, const float* __restrict__ dt_bias,
    const float* __restrict__ A_log, float* __restrict__ dt_out,
    float* __restrict__ dA_out)
{
    int idx = blockIdx.x * 256 + threadIdx.x;
    if (idx >= ROWS * NHEADS) return;
    int h = idx & (NHEADS - 1);
    int row = idx >> 3;
    float raw = zx[(size_t)row * D_IN_PROJ + (D_IN_PROJ - NHEADS) + h] + dt_bias[h];
    float dt = (raw > 20.0f) ? raw : log1pf(expf(raw));
    float A = -expf(A_log[h]);
    dt_out[idx] = dt;
    dA_out[idx] = expf(dt * A);
}

// ---------------- recurrent selective scan, smem-staged, cp.async d-buffer ----
// grid: (8 pb, 8 h, 2 b) = 128 blocks; block: 256 threads (8 warps).
// warp w owns p-rows {2w, 2w+1} (group = lane>>4); lane-in-group li owns
// state columns n in {li*4..+3} U {64+li*4..+3} (8 per thread, conflict-free).
__global__ __launch_bounds__(256) void scan2_kernel(
    const float* __restrict__ xbc, const float* __restrict__ dt_g,
    const float* __restrict__ dA_g, const float* __restrict__ D_skip,
    float* __restrict__ y_out)
{
    __shared__ float Bs[2][T_CHUNK][128];
    __shared__ float Cs[2][T_CHUNK][128];
    __shared__ float xs[2][T_CHUNK][P_BLK];
    __shared__ float ds[2][T_CHUNK][2];       // (dt, dA)
    __shared__ float ys[T_CHUNK][P_BLK];

    const int b = blockIdx.z, h = blockIdx.y, pb = blockIdx.x;
    const int tid = threadIdx.x;
    const int lane = tid & 31;
    const int warp = tid >> 5;
    const int lg = lane >> 4;                  // group 0/1
    const int li = lane & 15;
    const int p_local = warp * 2 + lg;         // 0..15
    const int n0 = li * 4;

    const float Dsk = D_skip[h];
    const float* xb  = xbc  + (size_t)b * SEQ * CONV_DIM;
    const float* dtp = dt_g + (size_t)b * SEQ * NHEADS + h;
    const float* dAp = dA_g + (size_t)b * SEQ * NHEADS + h;

    // ---- chunk loader ----
    auto load_chunk = [&](int c, int buf) {
        int t0 = c * T_CHUNK;
        // B: 512 float4, C: 512 float4 -> 2 each per thread
        #pragma unroll
        for (int it = 0; it < 2; it++) {
            int i = tid + it * 256;            // 0..511
            int t = i >> 5;
            int n4 = (i & 31) * 4;
            const float* row = xb + (size_t)(t0 + t) * CONV_DIM;
            cp_async16(&Bs[buf][t][n4], row + D_INNER + n4);
            cp_async16(&Cs[buf][t][n4], row + D_INNER + D_STATE + n4);
        }
        // x: 64 float4
        if (tid < 64) {
            int t = tid >> 2;
            int pi = (tid & 3) * 4;
            const float* row = xb + (size_t)(t0 + t) * CONV_DIM;
            cp_async16(&xs[buf][t][pi], row + h * HEADDIM + pb * P_BLK + pi);
        }
        // dt/dA: 32 scalars
        if (tid < 32) {
            int t = tid >> 1;
            int w = tid & 1;
            const float* src = (w ? dAp : dtp) + (size_t)(t0 + t) * NHEADS;
            cp_async4(&ds[buf][t][w], src);
        }
        cp_commit();
    };

    float S[8];
    #pragma unroll
    for (int i = 0; i < 8; i++) S[i] = 0.0f;

    load_chunk(0, 0);

    for (int c = 0; c < N_CHUNKS; c++) {
        int buf = c & 1;
        if (c + 1 < N_CHUNKS) {
            load_chunk(c + 1, buf ^ 1);
            cp_wait<1>();
        } else {
            cp_wait<0>();
        }
        __syncthreads();

        #pragma unroll 4
        for (int t = 0; t < T_CHUNK; t++) {
            float2 dd = *(const float2*)ds[buf][t];
            float cdt = dd.x, cdA = dd.y;
            float x = xs[buf][t][p_local];
            float c0 = cdt * x;
            float4 b0 = *(const float4*)&Bs[buf][t][n0];
            float4 b1 = *(const float4*)&Bs[buf][t][n0 + 64];
            float4 q0 = *(const float4*)&Cs[buf][t][n0];
            float4 q1 = *(const float4*)&Cs[buf][t][n0 + 64];

            S[0] = fmaf(S[0], cdA, c0 * b0.x);
            S[1] = fmaf(S[1], cdA, c0 * b0.y);
            S[2] = fmaf(S[2], cdA, c0 * b0.z);
            S[3] = fmaf(S[3], cdA, c0 * b0.w);
            S[4] = fmaf(S[4], cdA, c0 * b1.x);
            S[5] = fmaf(S[5], cdA, c0 * b1.y);
            S[6] = fmaf(S[6], cdA, c0 * b1.z);
            S[7] = fmaf(S[7], cdA, c0 * b1.w);

            float y = S[0] * q0.x;
            y = fmaf(S[1], q0.y, y);
            y = fmaf(S[2], q0.z, y);
            y = fmaf(S[3], q0.w, y);
            y = fmaf(S[4], q1.x, y);
            y = fmaf(S[5], q1.y, y);
            y = fmaf(S[6], q1.z, y);
            y = fmaf(S[7], q1.w, y);

            // reduce over the 16-lane group (xor offsets stay in-group)
            #pragma unroll
            for (int o = 8; o; o >>= 1) y += __shfl_xor_sync(0xffffffffu, y, o);
            if (li == 0) ys[t][p_local] = fmaf(Dsk, x, y);
        }
        __syncthreads();

        // flush ys: 64 float4
        if (tid < 64) {
            int t = tid >> 2;
            int q = (tid & 3) * 4;
            float4 v = *(const float4*)&ys[t][q];
            size_t row = (size_t)b * SEQ + c * T_CHUNK + t;
            *(float4*)(y_out + row * D_INNER + h * HEADDIM + pb * P_BLK + q) = v;
        }
        // next loop's post-wait __syncthreads protects ys reuse
    }
}

// ---------------- gate with silu(z), then RMSNorm * gnorm_w ----------------
__global__ __launch_bounds__(256) void gate_kernel(
    const float* __restrict__ y, const float* __restrict__ zx,
    const float* __restrict__ gw, float* __restrict__ out)
{
    int row = blockIdx.x;
    int tid = threadIdx.x;
    int d = tid * 4;
    __shared__ float sm[8];

    float4 y4 = *(const float4*)(y + (size_t)row * D_INNER + d);
    float4 z4 = *(const float4*)(zx + (size_t)row * D_IN_PROJ + d);
    float g0 = y4.x * siluf(z4.x);
    float g1 = y4.y * siluf(z4.y);
    float g2 = y4.z * siluf(z4.z);
    float g3 = y4.w * siluf(z4.w);

    float ss = g0 * g0 + g1 * g1 + g2 * g2 + g3 * g3;
    #pragma unroll
    for (int o = 16; o; o >>= 1) ss += __shfl_xor_sync(0xffffffffu, ss, o);
    if ((tid & 31) == 0) sm[tid >> 5] = ss;
    __syncthreads();
    float tot = 0.f;
    #pragma unroll
    for (int i = 0; i < 8; i++) tot += sm[i];
    float scale = rsqrtf(tot * (1.0f / (float)D_INNER) + EPS);

    float4 w4 = *(const float4*)(gw + d);
    float4 o4 = make_float4(g0 * scale * w4.x, g1 * scale * w4.y,
                            g2 * scale * w4.z, g3 * scale * w4.w);
    *(float4*)(out + (size_t)row * D_INNER + d) = o4;
}

// ---------------- launch ----------------
extern "C" void kernel_launch(void* const* d_in, const int* in_sizes, int n_in,
                              void* d_out, int out_size)
{
    const float* hidden  = (const float*)d_in[0];
    const float* w_in    = (const float*)d_in[1];
    const float* conv_w  = (const float*)d_in[2];
    const float* conv_b  = (const float*)d_in[3];
    const float* dt_bias = (const float*)d_in[4];
    const float* A_log   = (const float*)d_in[5];
    const float* D_skip  = (const float*)d_in[6];
    const float* gnorm_w = (const float*)d_in[7];
    const float* w_out   = (const float*)d_in[8];
    const float* ln1_w   = (const float*)d_in[9];
    const float* ln1_b   = (const float*)d_in[10];
    const float* ln2_w   = (const float*)d_in[11];
    const float* ln2_b   = (const float*)d_in[12];
    const float* mlp_w   = (const float*)d_in[13];
    const float* mlp_b   = (const float*)d_in[14];
    float* outp = (float*)d_out;

    float *h1, *zx, *xbc, *dt, *dA, *y, *gg, *res2, *h2;
    cudaGetSymbolAddress((void**)&h1,   g_h1);
    cudaGetSymbolAddress((void**)&zx,   g_zx);
    cudaGetSymbolAddress((void**)&xbc,  g_xbc);
    cudaGetSymbolAddress((void**)&dt,   g_dt);
    cudaGetSymbolAddress((void**)&dA,   g_dA);
    cudaGetSymbolAddress((void**)&y,    g_y);
    cudaGetSymbolAddress((void**)&gg,   g_g);
    cudaGetSymbolAddress((void**)&res2, g_res2);
    cudaGetSymbolAddress((void**)&h2,   g_h2);

    // 1) ln1
    ln_kernel<<<ROWS, 128>>>(hidden, ln1_w, ln1_b, h1);

    // 2) in_proj: zx[4096,2312] = h1[4096,128] @ w_in[2312,128]^T
    {
        dim3 grid((D_IN_PROJ + 63) / 64, ROWS / 128);
        gemm_tn128<<<grid, 256>>>(h1, D_MODEL, w_in, D_MODEL,
                                  zx, D_IN_PROJ, D_IN_PROJ, D_MODEL);
    }

    // 3) conv + silu
    {
        int total = B_SZ * SEQ * CONV_DIM;
        conv_kernel<<<(total + 255) / 256, 256>>>(zx, conv_w, conv_b, xbc);
    }

    // 4) dt / dA
    dt_kernel<<<(ROWS * NHEADS + 255) / 256, 256>>>(zx, dt_bias, A_log, dt, dA);

    // 5) scan (smem-staged)
    {
        dim3 grid(HEADDIM / P_BLK, NHEADS, B_SZ);   // (8, 8, 2)
        scan2_kernel<<<grid, 256>>>(xbc, dt, dA, D_skip, y);
    }

    // 6) gate + rmsnorm
    gate_kernel<<<ROWS, 256>>>(y, zx, gnorm_w, gg);

    // 7) out_proj + residual: res2 = gg @ w_out^T + hidden
    {
        dim3 grid((D_MODEL + 63) / 64, ROWS / 64);
        gemm_tn64<true, false><<<grid, 256>>>(gg, D_INNER, w_out, D_INNER,
                                              res2, D_MODEL, D_MODEL, D_INNER,
                                              hidden, nullptr);
    }

    // 8) ln2
    ln_kernel<<<ROWS, 128>>>(res2, ln2_w, ln2_b, h2);

    // 9) mlp: out = h2 @ mlp_w^T + mlp_b
    {
        dim3 grid((D_MODEL + 63) / 64, ROWS / 64);
        gemm_tn64<false, true><<<grid, 256>>>(h2, D_MODEL, mlp_w, D_MODEL,
                                              outp, D_MODEL, D_MODEL, D_MODEL,
                                              nullptr, mlp_b);
    }
    (void)in_sizes; (void)n_in; (void)out_size;
}

// round 3
// speedup vs baseline: 2.3267x; 1.5710x over previous
#include <cuda_runtime.h>
#include <cuda_bf16.h>
#include <cstdint>

#define B_SZ 2
#define SEQ 2048
#define ROWS (B_SZ * SEQ)          // 4096
#define D_MODEL 128
#define D_INNER 1024
#define NHEADS 8
#define HEADDIM 128
#define D_STATE 128
#define D_CONV 4
#define CONV_DIM (D_INNER + 2 * D_STATE)   // 1280
#define D_IN_PROJ (2 * D_INNER + 2 * D_STATE + NHEADS)  // 2312
#define EPS 1e-5f

#define QC 64                      // chunk length
#define NCH (SEQ / QC)             // 32 chunks
#define NBH (B_SZ * NHEADS)        // 16

// ---------------- scratch (no allocations allowed) ----------------
__device__ float g_h1[ROWS * D_MODEL];
__device__ float g_zx[ROWS * D_IN_PROJ];
__device__ float g_xbc[ROWS * CONV_DIM];
__device__ float g_dtT[NBH * SEQ];               // dt, [b*8+h][t]
__device__ float g_dtAT[NBH * SEQ];              // dt*A, [b*8+h][t]
__device__ float g_G[B_SZ * NCH * QC * QC];      // C B^T per (b,c): 1MB
__device__ float g_T[NBH * NCH * HEADDIM * D_STATE];   // 33.5MB
__device__ float g_Sp[NBH * NCH * HEADDIM * D_STATE];  // 33.5MB
__device__ float g_Lam[NBH * NCH];
__device__ float g_y[ROWS * D_INNER];
__device__ float g_g[ROWS * D_INNER];
__device__ float g_res2[ROWS * D_MODEL];
__device__ float g_h2[ROWS * D_MODEL];

__device__ __forceinline__ float siluf(float v) {
    return v / (1.0f + expf(-v));
}

// ---------------- LayerNorm: one block (128 thr) per row ----------------
__global__ __launch_bounds__(128) void ln_kernel(
    const float* __restrict__ x, const float* __restrict__ w,
    const float* __restrict__ b, float* __restrict__ out)
{
    int row = blockIdx.x;
    int tid = threadIdx.x;
    __shared__ float sm[4];
    float v = x[(size_t)row * D_MODEL + tid];

    float s = v;
    #pragma unroll
    for (int o = 16; o; o >>= 1) s += __shfl_xor_sync(0xffffffffu, s, o);
    if ((tid & 31) == 0) sm[tid >> 5] = s;
    __syncthreads();
    float mean = (sm[0] + sm[1] + sm[2] + sm[3]) * (1.0f / 128.0f);
    __syncthreads();

    float d = v - mean;
    float q = d * d;
    #pragma unroll
    for (int o = 16; o; o >>= 1) q += __shfl_xor_sync(0xffffffffu, q, o);
    if ((tid & 31) == 0) sm[tid >> 5] = q;
    __syncthreads();
    float var = (sm[0] + sm[1] + sm[2] + sm[3]) * (1.0f / 128.0f);

    out[(size_t)row * D_MODEL + tid] = d * rsqrtf(var + EPS) * w[tid] + b[tid];
}

// ---------------- GEMM 128x64x32, 256 threads, 8x4 regtile ----------------
__global__ __launch_bounds__(256) void gemm_tn128(
    const float* __restrict__ A, int lda,
    const float* __restrict__ W, int ldw,
    float* __restrict__ C, int ldc,
    int N, int K)
{
    __shared__ float As[32][132];
    __shared__ float Ws[32][68];

    int tid = threadIdx.x;
    int tx = tid & 15;
    int ty = tid >> 4;
    int m0 = blockIdx.y * 128;
    int n0 = blockIdx.x * 64;

    int arow = tid >> 3;
    int kv = (tid & 7) * 4;

    float acc[8][4];
    #pragma unroll
    for (int i = 0; i < 8; i++)
        #pragma unroll
        for (int j = 0; j < 4; j++) acc[i][j] = 0.0f;

    for (int k0 = 0; k0 < K; k0 += 32) {
        #pragma unroll
        for (int rr = 0; rr < 4; rr++) {
            int row = arow + rr * 32;
            float4 av = *(const float4*)(A + (size_t)(m0 + row) * lda + k0 + kv);
            As[kv + 0][row] = av.x;
            As[kv + 1][row] = av.y;
            As[kv + 2][row] = av.z;
            As[kv + 3][row] = av.w;
        }
        #pragma unroll
        for (int rr = 0; rr < 2; rr++) {
            int row = arow + rr * 32;
            int wr = n0 + row;
            float4 wv = make_float4(0.f, 0.f, 0.f, 0.f);
            if (wr < N) wv = *(const float4*)(W + (size_t)wr * ldw + k0 + kv);
            Ws[kv + 0][row] = wv.x;
            Ws[kv + 1][row] = wv.y;
            Ws[kv + 2][row] = wv.z;
            Ws[kv + 3][row] = wv.w;
        }
        __syncthreads();

        #pragma unroll
        for (int kk = 0; kk < 32; kk++) {
            float4 a0 = *(const float4*)&As[kk][ty * 8];
            float4 a1 = *(const float4*)&As[kk][ty * 8 + 4];
            float4 w  = *(const float4*)&Ws[kk][tx * 4];
            float af[8] = {a0.x, a0.y, a0.z, a0.w, a1.x, a1.y, a1.z, a1.w};
            float wf[4] = {w.x, w.y, w.z, w.w};
            #pragma unroll
            for (int i = 0; i < 8; i++)
                #pragma unroll
                for (int j = 0; j < 4; j++)
                    acc[i][j] = fmaf(af[i], wf[j], acc[i][j]);
        }
        __syncthreads();
    }

    #pragma unroll
    for (int i = 0; i < 8; i++) {
        int m = m0 + ty * 8 + i;
        #pragma unroll
        for (int j = 0; j < 4; j++) {
            int n = n0 + tx * 4 + j;
            if (n < N) C[(size_t)m * ldc + n] = acc[i][j];
        }
    }
}

// ---------------- GEMM 64x64x32 ----------------
template<bool RESID, bool BIAS>
__global__ __launch_bounds__(256) void gemm_tn64(
    const float* __restrict__ A, int lda,
    const float* __restrict__ W, int ldw,
    float* __restrict__ C, int ldc,
    int N, int K,
    const float* __restrict__ resid,
    const float* __restrict__ bias)
{
    __shared__ float As[32][68];
    __shared__ float Ws[32][68];

    int tid = threadIdx.x;
    int tx = tid & 15;
    int ty = tid >> 4;
    int m0 = blockIdx.y * 64;
    int n0 = blockIdx.x * 64;

    int arow = tid >> 3;
    int kv = (tid & 7) * 4;

    float acc[4][4];
    #pragma unroll
    for (int i = 0; i < 4; i++)
        #pragma unroll
        for (int j = 0; j < 4; j++) acc[i][j] = 0.0f;

    for (int k0 = 0; k0 < K; k0 += 32) {
        #pragma unroll
        for (int rr = 0; rr < 2; rr++) {
            int row = arow + rr * 32;
            float4 av = *(const float4*)(A + (size_t)(m0 + row) * lda + k0 + kv);
            As[kv + 0][row] = av.x;
            As[kv + 1][row] = av.y;
            As[kv + 2][row] = av.z;
            As[kv + 3][row] = av.w;
            int wr = n0 + row;
            float4 wv = make_float4(0.f, 0.f, 0.f, 0.f);
            if (wr < N) wv = *(const float4*)(W + (size_t)wr * ldw + k0 + kv);
            Ws[kv + 0][row] = wv.x;
            Ws[kv + 1][row] = wv.y;
            Ws[kv + 2][row] = wv.z;
            Ws[kv + 3][row] = wv.w;
        }
        __syncthreads();

        #pragma unroll
        for (int kk = 0; kk < 32; kk++) {
            float4 a = *(const float4*)&As[kk][ty * 4];
            float4 w = *(const float4*)&Ws[kk][tx * 4];
            float af[4] = {a.x, a.y, a.z, a.w};
            float wf[4] = {w.x, w.y, w.z, w.w};
            #pragma unroll
            for (int i = 0; i < 4; i++)
                #pragma unroll
                for (int j = 0; j < 4; j++)
                    acc[i][j] = fmaf(af[i], wf[j], acc[i][j]);
        }
        __syncthreads();
    }

    #pragma unroll
    for (int i = 0; i < 4; i++) {
        int m = m0 + ty * 4 + i;
        #pragma unroll
        for (int j = 0; j < 4; j++) {
            int n = n0 + tx * 4 + j;
            if (n < N) {
                float o = acc[i][j];
                if (RESID) o += resid[(size_t)m * ldc + n];
                if (BIAS)  o += bias[n];
                C[(size_t)m * ldc + n] = o;
            }
        }
    }
}

// ---------------- depthwise causal conv (k=4) + bias + silu ----------------
__global__ __launch_bounds__(256) void conv_kernel(
    const float* __restrict__ zx, const float* __restrict__ cw,
    const float* __restrict__ cb, float* __restrict__ out)
{
    int idx = blockIdx.x * 256 + threadIdx.x;
    if (idx >= B_SZ * SEQ * CONV_DIM) return;
    int c = idx % CONV_DIM;
    int t = (idx / CONV_DIM) & (SEQ - 1);
    int b = idx / (CONV_DIM * SEQ);

    const float* col = zx + (size_t)b * SEQ * D_IN_PROJ + D_INNER + c;
    float4 w = *(const float4*)(cw + c * 4);
    float acc = cb[c];
    if (t >= 3) acc = fmaf(w.x, col[(size_t)(t - 3) * D_IN_PROJ], acc);
    if (t >= 2) acc = fmaf(w.y, col[(size_t)(t - 2) * D_IN_PROJ], acc);
    if (t >= 1) acc = fmaf(w.z, col[(size_t)(t - 1) * D_IN_PROJ], acc);
    acc = fmaf(w.w, col[(size_t)t * D_IN_PROJ], acc);
    out[idx] = siluf(acc);
}

// -------- dt = softplus(raw+bias); store dt and dt*A in [bh][t] layout -----
__global__ __launch_bounds__(256) void dt2_kernel(
    const float* __restrict__ zx, const float* __restrict__ dt_bias,
    const float* __restrict__ A_log, float* __restrict__ dt_out,
    float* __restrict__ dtA_out)
{
    int idx = blockIdx.x * 256 + threadIdx.x;
    if (idx >= ROWS * NHEADS) return;
    int h = idx & (NHEADS - 1);
    int row = idx >> 3;            // b*SEQ + t
    int b = row >> 11;
    int t = row & (SEQ - 1);
    float raw = zx[(size_t)row * D_IN_PROJ + (D_IN_PROJ - NHEADS) + h] + dt_bias[h];
    float dt = (raw > 20.0f) ? raw : log1pf(expf(raw));
    float A = -expf(A_log[h]);
    int o = (b * NHEADS + h) * SEQ + t;
    dt_out[o] = dt;
    dtA_out[o] = dt * A;
}

// ---------------- K_G: G[i][j] = C_i . B_j per (b, chunk) -----------------
// grid (NCH, B_SZ), 256 thr. dyn smem: Cn[128][68] + Bn[128][68]
__global__ __launch_bounds__(256) void ssd_g_kernel(
    const float* __restrict__ xbc, float* __restrict__ G)
{
    extern __shared__ float sm[];
    float* Cn = sm;                  // [128][68]
    float* Bn = sm + 128 * 68;       // [128][68]

    int c = blockIdx.x, b = blockIdx.y;
    int tid = threadIdx.x;
    int t0 = c * QC;

    for (int q = tid; q < QC * 32; q += 256) {
        int t = q >> 5;
        int n4 = (q & 31) * 4;
        const float* row = xbc + (size_t)(b * SEQ + t0 + t) * CONV_DIM + D_INNER;
        float4 bv = *(const float4*)(row + n4);
        float4 cv = *(const float4*)(row + D_STATE + n4);
        #pragma unroll
        for (int l = 0; l < 4; l++) {
            Bn[(n4 + l) * 68 + t] = (&bv.x)[l];
            Cn[(n4 + l) * 68 + t] = (&cv.x)[l];
        }
    }
    __syncthreads();

    int ty = tid >> 4, tx = tid & 15;
    int i0 = ty * 4, j0 = tx * 4;
    float acc[4][4];
    #pragma unroll
    for (int i = 0; i < 4; i++)
        #pragma unroll
        for (int j = 0; j < 4; j++) acc[i][j] = 0.f;

    #pragma unroll 4
    for (int n = 0; n < D_STATE; n++) {
        float4 cv = *(const float4*)&Cn[n * 68 + i0];
        float4 bv = *(const float4*)&Bn[n * 68 + j0];
        float cf[4] = {cv.x, cv.y, cv.z, cv.w};
        float bf[4] = {bv.x, bv.y, bv.z, bv.w};
        #pragma unroll
        for (int i = 0; i < 4; i++)
            #pragma unroll
            for (int j = 0; j < 4; j++)
                acc[i][j] = fmaf(cf[i], bf[j], acc[i][j]);
    }

    float* Gp = G + (size_t)(b * NCH + c) * QC * QC;
    #pragma unroll
    for (int i = 0; i < 4; i++) {
        float4 v = make_float4(acc[i][0], acc[i][1], acc[i][2], acc[i][3]);
        *(float4*)(Gp + (i0 + i) * QC + j0) = v;
    }
}

// ---------------- K_intra: Y_intra + chunk state T + Lambda ----------------
// grid (NCH, NHEADS, B_SZ), 256 thr.
// dyn smem: Wt[64][68] + Xj[64][132] + Bj[64][132] + cs/dt/el (3*64)
__global__ __launch_bounds__(256) void ssd_intra_kernel(
    const float* __restrict__ xbc, const float* __restrict__ dt_t,
    const float* __restrict__ dtA_t, const float* __restrict__ G,
    const float* __restrict__ D_skip,
    float* __restrict__ y_out, float* __restrict__ T_out,
    float* __restrict__ Lam_out)
{
    extern __shared__ float sm[];
    float* Wt = sm;                         // [64][68]
    float* Xj = Wt + QC * 68;               // [64][132]
    float* Bj = Xj + QC * 132;              // [64][132]
    float* s_cs = Bj + QC * 132;            // 64
    float* s_dt = s_cs + QC;                // 64
    float* s_el = s_dt + QC;                // 64

    int c = blockIdx.x, h = blockIdx.y, b = blockIdx.z;
    int tid = threadIdx.x;
    int bh = b * NHEADS + h;
    int t0 = c * QC;

    if (tid < QC) {
        s_cs[tid] = dtA_t[(size_t)bh * SEQ + t0 + tid];
        s_dt[tid] = dt_t[(size_t)bh * SEQ + t0 + tid];
    }
    __syncthreads();
    // inclusive scan of dtA -> cs
    #pragma unroll
    for (int off = 1; off < QC; off <<= 1) {
        float v = 0.f;
        if (tid < QC && tid >= off) v = s_cs[tid - off];
        __syncthreads();
        if (tid < QC) s_cs[tid] += v;
        __syncthreads();
    }
    if (tid < QC) s_el[tid] = __expf(s_cs[QC - 1] - s_cs[tid]) * s_dt[tid];
    if (tid == 0) Lam_out[bh * NCH + c] = __expf(s_cs[QC - 1]);

    // load X (head slice) and B, row-major [t][*] with pad 132
    for (int q = tid; q < QC * 32; q += 256) {
        int t = q >> 5;
        int n4 = (q & 31) * 4;
        const float* row = xbc + (size_t)(b * SEQ + t0 + t) * CONV_DIM;
        *(float4*)&Xj[t * 132 + n4] = *(const float4*)(row + h * HEADDIM + n4);
        *(float4*)&Bj[t * 132 + n4] = *(const float4*)(row + D_INNER + n4);
    }

    // W = mask .* G  (read G from global, write transposed Wt[j][i])
    int ty = tid >> 4, tx = tid & 15;
    {
        int i0 = ty * 4, j0 = tx * 4;
        const float* Gp = G + (size_t)(b * NCH + c) * QC * QC;
        #pragma unroll
        for (int ii = 0; ii < 4; ii++) {
            int i = i0 + ii;
            float4 gv = *(const float4*)(Gp + i * QC + j0);
            float gf[4] = {gv.x, gv.y, gv.z, gv.w};
            #pragma unroll
            for (int jj = 0; jj < 4; jj++) {
                int j = j0 + jj;
                float w = 0.f;
                if (j <= i) w = __expf(s_cs[i] - s_cs[j]) * s_dt[j] * gf[jj];
                Wt[j * 68 + i] = w;
            }
        }
    }
    __syncthreads();

    float Dsk = D_skip[h];

    // ---- Y_intra[i][p] = sum_j Wt[j][i] * Xj[j][p],  j <= i  ----
    {
        int i0 = ty * 4, p0 = tx * 8;
        float acc[4][8];
        #pragma unroll
        for (int i = 0; i < 4; i++)
            #pragma unroll
            for (int p = 0; p < 8; p++) acc[i][p] = 0.f;

        int jmax = i0 + 4;               // rows beyond i have W=0
        for (int j = 0; j < jmax; j++) {
            float4 wv = *(const float4*)&Wt[j * 68 + i0];
            float4 xa = *(const float4*)&Xj[j * 132 + p0];
            float4 xb = *(const float4*)&Xj[j * 132 + p0 + 4];
            float wf[4] = {wv.x, wv.y, wv.z, wv.w};
            float xf[8] = {xa.x, xa.y, xa.z, xa.w, xb.x, xb.y, xb.z, xb.w};
            #pragma unroll
            for (int i = 0; i < 4; i++)
                #pragma unroll
                for (int p = 0; p < 8; p++)
                    acc[i][p] = fmaf(wf[i], xf[p], acc[i][p]);
        }
        // y = Y_intra + Dsk * x
        #pragma unroll
        for (int ii = 0; ii < 4; ii++) {
            int i = i0 + ii;
            size_t row = (size_t)(b * SEQ + t0 + i);
            float* yp = y_out + row * D_INNER + h * HEADDIM + p0;
            float4 x0 = *(const float4*)&Xj[i * 132 + p0];
            float4 x1 = *(const float4*)&Xj[i * 132 + p0 + 4];
            float4 o0 = make_float4(fmaf(Dsk, x0.x, acc[ii][0]),
                                    fmaf(Dsk, x0.y, acc[ii][1]),
                                    fmaf(Dsk, x0.z, acc[ii][2]),
                                    fmaf(Dsk, x0.w, acc[ii][3]));
            float4 o1 = make_float4(fmaf(Dsk, x1.x, acc[ii][4]),
                                    fmaf(Dsk, x1.y, acc[ii][5]),
                                    fmaf(Dsk, x1.z, acc[ii][6]),
                                    fmaf(Dsk, x1.w, acc[ii][7]));
            *(float4*)yp = o0;
            *(float4*)(yp + 4) = o1;
        }
    }

    // ---- T[p][n] = sum_j el[j] * Xj[j][p] * Bj[j][n] ----
    {
        int p0 = ty * 8, n0 = tx * 8;
        float acc[8][8];
        #pragma unroll
        for (int p = 0; p < 8; p++)
            #pragma unroll
            for (int n = 0; n < 8; n++) acc[p][n] = 0.f;

        #pragma unroll 2
        for (int j = 0; j < QC; j++) {
            float el = s_el[j];
            float4 xa = *(const float4*)&Xj[j * 132 + p0];
            float4 xb = *(const float4*)&Xj[j * 132 + p0 + 4];
            float4 ba = *(const float4*)&Bj[j * 132 + n0];
            float4 bb = *(const float4*)&Bj[j * 132 + n0 + 4];
            float xf[8] = {el * xa.x, el * xa.y, el * xa.z, el * xa.w,
                           el * xb.x, el * xb.y, el * xb.z, el * xb.w};
            float bf[8] = {ba.x, ba.y, ba.z, ba.w, bb.x, bb.y, bb.z, bb.w};
            #pragma unroll
            for (int p = 0; p < 8; p++)
                #pragma unroll
                for (int n = 0; n < 8; n++)
                    acc[p][n] = fmaf(xf[p], bf[n], acc[p][n]);
        }
        float* Tp = T_out + ((size_t)bh * NCH + c) * (HEADDIM * D_STATE);
        #pragma unroll
        for (int pp = 0; pp < 8; pp++) {
            float4 v0 = make_float4(acc[pp][0], acc[pp][1], acc[pp][2], acc[pp][3]);
            float4 v1 = make_float4(acc[pp][4], acc[pp][5], acc[pp][6], acc[pp][7]);
            *(float4*)(Tp + (p0 + pp) * D_STATE + n0) = v0;
            *(float4*)(Tp + (p0 + pp) * D_STATE + n0 + 4) = v1;
        }
    }
}

// ---------------- K_inter: sequential chunk-state recurrence ----------------
__global__ __launch_bounds__(256) void ssd_inter_kernel(
    const float* __restrict__ T, const float* __restrict__ Lam,
    float* __restrict__ Sp)
{
    int gid = blockIdx.x * 256 + threadIdx.x;   // 0 .. 16*16384-1
    int bh = gid >> 14;
    int pn = gid & 16383;
    size_t base = ((size_t)bh << 19);           // bh * 32 * 16384
    float S = 0.f;
    #pragma unroll 4
    for (int c = 0; c < NCH; c++) {
        size_t idx = base + ((size_t)c << 14) + pn;
        if (c) Sp[idx] = S;
        S = fmaf(Lam[bh * NCH + c], S, T[idx]);
    }
}

// ---------------- K_out: y += exp(cs_i) * C_i . Sprev[p,:] ----------------
// grid (NCH, NHEADS, B_SZ); skip c==0. dyn smem: Cn[128][68]+Spn[128][132]+cs
__global__ __launch_bounds__(256) void ssd_out_kernel(
    const float* __restrict__ xbc, const float* __restrict__ dtA_t,
    const float* __restrict__ Sp, float* __restrict__ y_out)
{
    int c = blockIdx.x;
    if (c == 0) return;
    extern __shared__ float sm[];
    float* Cn = sm;                       // [128][68]
    float* Spn = Cn + 128 * 68;           // [128][132]
    float* s_cs = Spn + 128 * 132;        // 64

    int h = blockIdx.y, b = blockIdx.z;
    int tid = threadIdx.x;
    int bh = b * NHEADS + h;
    int t0 = c * QC;

    if (tid < QC) s_cs[tid] = dtA_t[(size_t)bh * SEQ + t0 + tid];
    __syncthreads();
    #pragma unroll
    for (int off = 1; off < QC; off <<= 1) {
        float v = 0.f;
        if (tid < QC && tid >= off) v = s_cs[tid - off];
        __syncthreads();
        if (tid < QC) s_cs[tid] += v;
        __syncthreads();
    }

    // load C transposed: Cn[n][i]
    for (int q = tid; q < QC * 32; q += 256) {
        int t = q >> 5;
        int n4 = (q & 31) * 4;
        const float* row = xbc + (size_t)(b * SEQ + t0 + t) * CONV_DIM
                         + D_INNER + D_STATE;
        float4 v = *(const float4*)(row + n4);
        #pragma unroll
        for (int l = 0; l < 4; l++) Cn[(n4 + l) * 68 + t] = (&v.x)[l];
    }
    // load Sprev transposed: Spn[n][p]
    const float* Spsrc = Sp + ((size_t)bh * NCH + c) * (HEADDIM * D_STATE);
    for (int q = tid; q < HEADDIM * 32; q += 256) {
        int p = q >> 5;
        int n4 = (q & 31) * 4;
        float4 v = *(const float4*)(Spsrc + p * D_STATE + n4);
        #pragma unroll
        for (int l = 0; l < 4; l++) Spn[(n4 + l) * 132 + p] = (&v.x)[l];
    }
    __syncthreads();

    int ty = tid >> 4, tx = tid & 15;
    int i0 = ty * 4, p0 = tx * 8;
    float acc[4][8];
    #pragma unroll
    for (int i = 0; i < 4; i++)
        #pragma unroll
        for (int p = 0; p < 8; p++) acc[i][p] = 0.f;

    #pragma unroll 2
    for (int n = 0; n < D_STATE; n++) {
        float4 cv = *(const float4*)&Cn[n * 68 + i0];
        float4 sa = *(const float4*)&Spn[n * 132 + p0];
        float4 sb = *(const float4*)&Spn[n * 132 + p0 + 4];
        float cf[4] = {cv.x, cv.y, cv.z, cv.w};
        float sf[8] = {sa.x, sa.y, sa.z, sa.w, sb.x, sb.y, sb.z, sb.w};
        #pragma unroll
        for (int i = 0; i < 4; i++)
            #pragma unroll
            for (int p = 0; p < 8; p++)
                acc[i][p] = fmaf(cf[i], sf[p], acc[i][p]);
    }

    #pragma unroll
    for (int ii = 0; ii < 4; ii++) {
        int i = i0 + ii;
        float e = __expf(s_cs[i]);
        size_t row = (size_t)(b * SEQ + t0 + i);
        float* yp = y_out + row * D_INNER + h * HEADDIM + p0;
        float4 y0 = *(const float4*)yp;
        float4 y1 = *(const float4*)(yp + 4);
        y0.x = fmaf(e, acc[ii][0], y0.x);
        y0.y = fmaf(e, acc[ii][1], y0.y);
        y0.z = fmaf(e, acc[ii][2], y0.z);
        y0.w = fmaf(e, acc[ii][3], y0.w);
        y1.x = fmaf(e, acc[ii][4], y1.x);
        y1.y = fmaf(e, acc[ii][5], y1.y);
        y1.z = fmaf(e, acc[ii][6], y1.z);
        y1.w = fmaf(e, acc[ii][7], y1.w);
        *(float4*)yp = y0;
        *(float4*)(yp + 4) = y1;
    }
}

// ---------------- gate with silu(z), then RMSNorm * gnorm_w ----------------
__global__ __launch_bounds__(256) void gate_kernel(
    const float* __restrict__ y, const float* __restrict__ zx,
    const float* __restrict__ gw, float* __restrict__ out)
{
    int row = blockIdx.x;
    int tid = threadIdx.x;
    int d = tid * 4;
    __shared__ float sm[8];

    float4 y4 = *(const float4*)(y + (size_t)row * D_INNER + d);
    float4 z4 = *(const float4*)(zx + (size_t)row * D_IN_PROJ + d);
    float g0 = y4.x * siluf(z4.x);
    float g1 = y4.y * siluf(z4.y);
    float g2 = y4.z * siluf(z4.z);
    float g3 = y4.w * siluf(z4.w);

    float ss = g0 * g0 + g1 * g1 + g2 * g2 + g3 * g3;
    #pragma unroll
    for (int o = 16; o; o >>= 1) ss += __shfl_xor_sync(0xffffffffu, ss, o);
    if ((tid & 31) == 0) sm[tid >> 5] = ss;
    __syncthreads();
    float tot = 0.f;
    #pragma unroll
    for (int i = 0; i < 8; i++) tot += sm[i];
    float scale = rsqrtf(tot * (1.0f / (float)D_INNER) + EPS);

    float4 w4 = *(const float4*)(gw + d);
    float4 o4 = make_float4(g0 * scale * w4.x, g1 * scale * w4.y,
                            g2 * scale * w4.z, g3 * scale * w4.w);
    *(float4*)(out + (size_t)row * D_INNER + d) = o4;
}

// ---------------- launch ----------------
extern "C" void kernel_launch(void* const* d_in, const int* in_sizes, int n_in,
                              void* d_out, int out_size)
{
    const float* hidden  = (const float*)d_in[0];
    const float* w_in    = (const float*)d_in[1];
    const float* conv_w  = (const float*)d_in[2];
    const float* conv_b  = (const float*)d_in[3];
    const float* dt_bias = (const float*)d_in[4];
    const float* A_log   = (const float*)d_in[5];
    const float* D_skip  = (const float*)d_in[6];
    const float* gnorm_w = (const float*)d_in[7];
    const float* w_out   = (const float*)d_in[8];
    const float* ln1_w   = (const float*)d_in[9];
    const float* ln1_b   = (const float*)d_in[10];
    const float* ln2_w   = (const float*)d_in[11];
    const float* ln2_b   = (const float*)d_in[12];
    const float* mlp_w   = (const float*)d_in[13];
    const float* mlp_b   = (const float*)d_in[14];
    float* outp = (float*)d_out;

    float *h1, *zx, *xbc, *dtT, *dtAT, *Gm, *Tm, *Spm, *Lam, *y, *gg, *res2, *h2;
    cudaGetSymbolAddress((void**)&h1,   g_h1);
    cudaGetSymbolAddress((void**)&zx,   g_zx);
    cudaGetSymbolAddress((void**)&xbc,  g_xbc);
    cudaGetSymbolAddress((void**)&dtT,  g_dtT);
    cudaGetSymbolAddress((void**)&dtAT, g_dtAT);
    cudaGetSymbolAddress((void**)&Gm,   g_G);
    cudaGetSymbolAddress((void**)&Tm,   g_T);
    cudaGetSymbolAddress((void**)&Spm,  g_Sp);
    cudaGetSymbolAddress((void**)&Lam,  g_Lam);
    cudaGetSymbolAddress((void**)&y,    g_y);
    cudaGetSymbolAddress((void**)&gg,   g_g);
    cudaGetSymbolAddress((void**)&res2, g_res2);
    cudaGetSymbolAddress((void**)&h2,   g_h2);

    const int smem_g     = (128 * 68 * 2) * 4;                       // 69632
    const int smem_intra = (QC * 68 + QC * 132 * 2 + 3 * QC) * 4;    // 85760
    const int smem_out   = (128 * 68 + 128 * 132 + QC) * 4;         // 102656
    cudaFuncSetAttribute(ssd_g_kernel,
        cudaFuncAttributeMaxDynamicSharedMemorySize, smem_g);
    cudaFuncSetAttribute(ssd_intra_kernel,
        cudaFuncAttributeMaxDynamicSharedMemorySize, smem_intra);
    cudaFuncSetAttribute(ssd_out_kernel,
        cudaFuncAttributeMaxDynamicSharedMemorySize, smem_out);

    // 1) ln1
    ln_kernel<<<ROWS, 128>>>(hidden, ln1_w, ln1_b, h1);

    // 2) in_proj
    {
        dim3 grid((D_IN_PROJ + 63) / 64, ROWS / 128);
        gemm_tn128<<<grid, 256>>>(h1, D_MODEL, w_in, D_MODEL,
                                  zx, D_IN_PROJ, D_IN_PROJ, D_MODEL);
    }

    // 3) conv + silu
    {
        int total = B_SZ * SEQ * CONV_DIM;
        conv_kernel<<<(total + 255) / 256, 256>>>(zx, conv_w, conv_b, xbc);
    }

    // 4) dt / dtA (transposed layout)
    dt2_kernel<<<(ROWS * NHEADS + 255) / 256, 256>>>(zx, dt_bias, A_log, dtT, dtAT);

    // 5) chunked SSD
    {
        dim3 gg_(NCH, B_SZ);
        ssd_g_kernel<<<gg_, 256, smem_g>>>(xbc, Gm);

        dim3 gi(NCH, NHEADS, B_SZ);
        ssd_intra_kernel<<<gi, 256, smem_intra>>>(xbc, dtT, dtAT, Gm, D_skip,
                                                  y, Tm, Lam);

        ssd_inter_kernel<<<(NBH * HEADDIM * D_STATE) / 256, 256>>>(Tm, Lam, Spm);

        ssd_out_kernel<<<gi, 256, smem_out>>>(xbc, dtAT, Spm, y);
    }

    // 6) gate + rmsnorm
    gate_kernel<<<ROWS, 256>>>(y, zx, gnorm_w, gg);

    // 7) out_proj + residual
    {
        dim3 grid((D_MODEL + 63) / 64, ROWS / 64);
        gemm_tn64<true, false><<<grid, 256>>>(gg, D_INNER, w_out, D_INNER,
                                              res2, D_MODEL, D_MODEL, D_INNER,
                                              hidden, nullptr);
    }

    // 8) ln2
    ln_kernel<<<ROWS, 128>>>(res2, ln2_w, ln2_b, h2);

    // 9) mlp
    {
        dim3 grid((D_MODEL + 63) / 64, ROWS / 64);
        gemm_tn64<false, true><<<grid, 256>>>(h2, D_MODEL, mlp_w, D_MODEL,
                                              outp, D_MODEL, D_MODEL, D_MODEL,
                                              nullptr, mlp_b);
    }
    (void)in_sizes; (void)n_in; (void)out_size;
}